// round 10
// baseline (speedup 1.0000x reference)
#include <cuda_runtime.h>
#include <math.h>

// Problem constants
#define BB   32
#define TT   128
#define LL   64
#define DIN  512
#define HH   512
#define DCTX 512
#define ATT  256
#define NG   2048            // 4 gates * 512
#define BT512 (BB*TT*512)    // 2097152

// Scratch (static __device__ — no allocation allowed)
__device__ float g_xcat[BB*TT*NG];      // [(b*128+t)][2048]  x-projections (+bias)
__device__ float g_ctxtr[BB*LL*ATT];    // [(b*64+l)][256]    context @ att_ctx_W1 + b1
__device__ float g_pre[2][BB*NG];       // k-split partials of h@U + ctx@C
__device__ float g_h[BB*HH];
__device__ float g_c[BB*HH];
__device__ float g_cv[BB*DCTX];

__global__ void k_zero() {
    int i = blockIdx.x * blockDim.x + threadIdx.x;
    if (i < BB*HH) { g_h[i] = 0.f; g_c[i] = 0.f; }
}

// ---------------------------------------------------------------------------
// Precompute: xcat[(b*T+t)][g*512+h] = X[b,t,:] @ W_g[:,h] + b_g[h]
// 64x64 output tile per block, 256 threads, 4x4 per thread, BK=16.
// ---------------------------------------------------------------------------
__global__ void k_xproj(const float* __restrict__ X,
                        const float* __restrict__ W0, const float* __restrict__ W1,
                        const float* __restrict__ W2, const float* __restrict__ W3,
                        const float* __restrict__ b0, const float* __restrict__ b1_,
                        const float* __restrict__ b2_, const float* __restrict__ b3)
{
    const int R0 = blockIdx.y * 64;
    const int C0 = blockIdx.x * 64;
    const int g  = C0 >> 9;
    const float* W  = (g==0)?W0:(g==1)?W1:(g==2)?W2:W3;
    const float* bs = (g==0)?b0:(g==1)?b1_:(g==2)?b2_:b3;
    const int ch0 = C0 & 511;

    __shared__ float As[16][64];
    __shared__ float Bs[16][64];

    const int tid = threadIdx.x;
    const int tx = tid & 15, ty = tid >> 4;
    float acc[4][4] = {};

    for (int k0 = 0; k0 < 512; k0 += 16) {
        {   // A tile: 64 rows x 16 k
            int row = tid >> 2;
            int kq  = (tid & 3) * 4;
            float4 v = *(const float4*)&X[(size_t)(R0+row)*512 + k0 + kq];
            As[kq+0][row]=v.x; As[kq+1][row]=v.y; As[kq+2][row]=v.z; As[kq+3][row]=v.w;
        }
        {   // B tile: 16 k x 64 cols
            int kr = tid >> 4;
            int cq = (tid & 15) * 4;
            float4 v = *(const float4*)&W[(size_t)(k0+kr)*512 + ch0 + cq];
            *(float4*)&Bs[kr][cq] = v;
        }
        __syncthreads();
        #pragma unroll
        for (int kk = 0; kk < 16; kk++) {
            float4 av = *(const float4*)&As[kk][ty*4];
            float4 bv = *(const float4*)&Bs[kk][tx*4];
            acc[0][0]+=av.x*bv.x; acc[0][1]+=av.x*bv.y; acc[0][2]+=av.x*bv.z; acc[0][3]+=av.x*bv.w;
            acc[1][0]+=av.y*bv.x; acc[1][1]+=av.y*bv.y; acc[1][2]+=av.y*bv.z; acc[1][3]+=av.y*bv.w;
            acc[2][0]+=av.z*bv.x; acc[2][1]+=av.z*bv.y; acc[2][2]+=av.z*bv.z; acc[2][3]+=av.z*bv.w;
            acc[3][0]+=av.w*bv.x; acc[3][1]+=av.w*bv.y; acc[3][2]+=av.w*bv.z; acc[3][3]+=av.w*bv.w;
        }
        __syncthreads();
    }
    float4 bias = *(const float4*)&bs[ch0 + tx*4];
    #pragma unroll
    for (int i = 0; i < 4; i++) {
        int row = R0 + ty*4 + i;
        float4 o;
        o.x = acc[i][0] + bias.x; o.y = acc[i][1] + bias.y;
        o.z = acc[i][2] + bias.z; o.w = acc[i][3] + bias.w;
        *(float4*)&g_xcat[(size_t)row*NG + C0 + tx*4] = o;
    }
}

// ctx_trans[(b*L+l)][a] = context[b,l,:] @ att_ctx_W1[:,a] + att_b1[a]
__global__ void k_ctxproj(const float* __restrict__ ctx,
                          const float* __restrict__ W,
                          const float* __restrict__ bias)
{
    const int R0 = blockIdx.y * 64;
    const int C0 = blockIdx.x * 64;

    __shared__ float As[16][64];
    __shared__ float Bs[16][64];

    const int tid = threadIdx.x;
    const int tx = tid & 15, ty = tid >> 4;
    float acc[4][4] = {};

    for (int k0 = 0; k0 < 512; k0 += 16) {
        {
            int row = tid >> 2;
            int kq  = (tid & 3) * 4;
            float4 v = *(const float4*)&ctx[(size_t)(R0+row)*512 + k0 + kq];
            As[kq+0][row]=v.x; As[kq+1][row]=v.y; As[kq+2][row]=v.z; As[kq+3][row]=v.w;
        }
        {
            int kr = tid >> 4;
            int cq = (tid & 15) * 4;
            float4 v = *(const float4*)&W[(size_t)(k0+kr)*ATT + C0 + cq];
            *(float4*)&Bs[kr][cq] = v;
        }
        __syncthreads();
        #pragma unroll
        for (int kk = 0; kk < 16; kk++) {
            float4 av = *(const float4*)&As[kk][ty*4];
            float4 bv = *(const float4*)&Bs[kk][tx*4];
            acc[0][0]+=av.x*bv.x; acc[0][1]+=av.x*bv.y; acc[0][2]+=av.x*bv.z; acc[0][3]+=av.x*bv.w;
            acc[1][0]+=av.y*bv.x; acc[1][1]+=av.y*bv.y; acc[1][2]+=av.y*bv.z; acc[1][3]+=av.y*bv.w;
            acc[2][0]+=av.z*bv.x; acc[2][1]+=av.z*bv.y; acc[2][2]+=av.z*bv.z; acc[2][3]+=av.z*bv.w;
            acc[3][0]+=av.w*bv.x; acc[3][1]+=av.w*bv.y; acc[3][2]+=av.w*bv.z; acc[3][3]+=av.w*bv.w;
        }
        __syncthreads();
    }
    float4 bias4 = *(const float4*)&bias[C0 + tx*4];
    #pragma unroll
    for (int i = 0; i < 4; i++) {
        int row = R0 + ty*4 + i;
        float4 o;
        o.x = acc[i][0] + bias4.x; o.y = acc[i][1] + bias4.y;
        o.z = acc[i][2] + bias4.z; o.w = acc[i][3] + bias4.w;
        *(float4*)&g_ctxtr[(size_t)row*ATT + C0 + tx*4] = o;
    }
}

// ---------------------------------------------------------------------------
// k_step_a: one block per batch.
//   Phase 1 (t>0): apply gate activations for step t-1 (pre + xcat), update
//                  h/c, write hs/cs outputs.
//   Phase 2 (t<T): attention with fresh h -> ctx_vec, write ctxs output.
//   t==T: update-only (final step).
// ---------------------------------------------------------------------------
__device__ __forceinline__ float sigf(float x) { return 1.f / (1.f + expf(-x)); }

__global__ void k_step_a(const float* __restrict__ mask,
                         const float* __restrict__ context,
                         const int*   __restrict__ cmask,
                         const float* __restrict__ attW1h,
                         const float* __restrict__ attW2,
                         const float* __restrict__ attb2,
                         float* __restrict__ out, int t)
{
    const int b   = blockIdx.x;
    const int tid = threadIdx.x;

    __shared__ float h_sm[512];
    __shared__ float s_sm[256];
    __shared__ float e_sm[64];
    __shared__ float inv_sm;

    if (t > 0) {
        const int tt = t - 1;
        const float m = mask[b*TT + tt];
        const float* xrow = &g_xcat[(size_t)(b*TT + tt)*NG];
        const float* p0 = &g_pre[0][b*NG];
        const float* p1 = &g_pre[1][b*NG];
        #pragma unroll
        for (int h0 = tid; h0 < 512; h0 += 256) {
            float Pi = xrow[h0]        + p0[h0]        + p1[h0];
            float Pf = xrow[512+h0]    + p0[512+h0]    + p1[512+h0];
            float Pc = xrow[1024+h0]   + p0[1024+h0]   + p1[1024+h0];
            float Po = xrow[1536+h0]   + p0[1536+h0]   + p1[1536+h0];
            float ig = sigf(Pi);
            float fg = sigf(Pf);
            float gg = tanhf(Pc);
            float og = sigf(Po);
            float co = g_c[b*512 + h0];
            float ho = g_h[b*512 + h0];
            float cn = fg*co + ig*gg;
            float hn = og*tanhf(cn);
            hn = (1.f - m)*ho + m*hn;
            cn = (1.f - m)*co + m*cn;
            g_h[b*512 + h0] = hn;
            g_c[b*512 + h0] = cn;
            h_sm[h0] = hn;
            out[(size_t)(b*TT + tt)*512 + h0]         = hn;
            out[BT512 + (size_t)(b*TT + tt)*512 + h0] = cn;
        }
    } else {
        for (int h0 = tid; h0 < 512; h0 += 256) h_sm[h0] = 0.f;
    }
    if (t == TT) return;       // final update-only launch (uniform exit)
    __syncthreads();

    // s[a] = h @ att_h_W1[:, a]
    {
        float acc = 0.f;
        #pragma unroll 8
        for (int k = 0; k < 512; k++)
            acc += h_sm[k] * attW1h[k*ATT + tid];
        s_sm[tid] = acc;
    }
    __syncthreads();

    // scores: raw[l] = sum_a tanh(ctxtr[b,l,a] + s[a]) * W2[a] + b2
    {
        const int w = tid >> 5, lane = tid & 31;
        for (int l = w; l < LL; l += 8) {
            float p = 0.f;
            const float* ct = &g_ctxtr[(size_t)(b*LL + l)*ATT];
            #pragma unroll
            for (int a = lane; a < ATT; a += 32)
                p += tanhf(ct[a] + s_sm[a]) * attW2[a];
            #pragma unroll
            for (int off = 16; off; off >>= 1)
                p += __shfl_down_sync(0xffffffffu, p, off);
            if (lane == 0) {
                float raw = p + attb2[0];
                e_sm[l] = expf(raw) * (float)cmask[b*LL + l];
            }
        }
    }
    __syncthreads();
    if (tid < 32) {
        float v = e_sm[tid] + e_sm[tid + 32];
        #pragma unroll
        for (int off = 16; off; off >>= 1)
            v += __shfl_down_sync(0xffffffffu, v, off);
        if (tid == 0) inv_sm = 1.f / v;
    }
    __syncthreads();
    const float inv = inv_sm;

    // ctx_vec[d] = (sum_l e[l]*context[b,l,d]) * inv
    for (int d = tid; d < 512; d += 256) {
        float acc = 0.f;
        #pragma unroll 8
        for (int l = 0; l < LL; l++)
            acc += e_sm[l] * context[(size_t)(b*LL + l)*512 + d];
        acc *= inv;
        g_cv[b*512 + d] = acc;
        out[2*BT512 + (size_t)(b*TT + t)*512 + d] = acc;
    }
}

// ---------------------------------------------------------------------------
// k_step_b: pre[ks][b][col] = sum_{k in half ks} h[b,k]*U_g[k,h] + cv[b,k]*C_g[k,h]
// 128 blocks = 64 column tiles (32 cols) x 2 k-halves. 256 threads.
// thread = 4 consecutive cols (float4 weights) x 1 batch.
// ---------------------------------------------------------------------------
__global__ void k_step_b(const float* __restrict__ U0, const float* __restrict__ U1,
                         const float* __restrict__ U2, const float* __restrict__ U3,
                         const float* __restrict__ C0, const float* __restrict__ C1,
                         const float* __restrict__ C2, const float* __restrict__ C3)
{
    const int bid  = blockIdx.x;
    const int ct   = bid & 63;
    const int ks   = bid >> 6;
    const int col0 = ct * 32;
    const int g    = col0 >> 9;
    const int hb   = col0 & 511;
    const float* U = (g==0)?U0:(g==1)?U1:(g==2)?U2:U3;
    const float* C = (g==0)?C0:(g==1)?C1:(g==2)?C2:C3;

    const int tid = threadIdx.x;
    const int cq  = tid & 7;      // column quad within tile
    const int bb  = tid >> 3;     // batch

    __shared__ float h_sm[32][129];
    __shared__ float cv_sm[32][129];

    float4 acc = make_float4(0.f, 0.f, 0.f, 0.f);

    #pragma unroll
    for (int kt = 0; kt < 2; kt++) {
        const int kb = ks*256 + kt*128;
        for (int i = tid; i < 4096; i += 256) {
            int r = i >> 7, kk = i & 127;
            h_sm[r][kk]  = g_h[r*512 + kb + kk];
            cv_sm[r][kk] = g_cv[r*512 + kb + kk];
        }
        __syncthreads();
        #pragma unroll 8
        for (int kk = 0; kk < 128; kk++) {
            float4 wu = *(const float4*)&U[(size_t)(kb+kk)*512 + hb + cq*4];
            float4 wc = *(const float4*)&C[(size_t)(kb+kk)*512 + hb + cq*4];
            float hv = h_sm[bb][kk];
            float cv = cv_sm[bb][kk];
            acc.x += hv*wu.x + cv*wc.x;
            acc.y += hv*wu.y + cv*wc.y;
            acc.z += hv*wu.z + cv*wc.z;
            acc.w += hv*wu.w + cv*wc.w;
        }
        __syncthreads();
    }
    *(float4*)&g_pre[ks][bb*NG + col0 + cq*4] = acc;
}

// ---------------------------------------------------------------------------
extern "C" void kernel_launch(void* const* d_in, const int* in_sizes, int n_in,
                              void* d_out, int out_size)
{
    const float* X       = (const float*)d_in[0];
    const float* context = (const float*)d_in[1];
    const float* mask    = (const float*)d_in[2];
    const int*   cmask   = (const int*)  d_in[3];
    const float* W_i = (const float*)d_in[4];
    const float* U_i = (const float*)d_in[5];
    const float* C_i = (const float*)d_in[6];
    const float* b_i = (const float*)d_in[7];
    const float* W_f = (const float*)d_in[8];
    const float* U_f = (const float*)d_in[9];
    const float* C_f = (const float*)d_in[10];
    const float* b_f = (const float*)d_in[11];
    const float* W_c = (const float*)d_in[12];
    const float* U_c = (const float*)d_in[13];
    const float* C_c = (const float*)d_in[14];
    const float* b_c = (const float*)d_in[15];
    const float* W_o = (const float*)d_in[16];
    const float* U_o = (const float*)d_in[17];
    const float* C_o = (const float*)d_in[18];
    const float* b_o = (const float*)d_in[19];
    const float* attW1c = (const float*)d_in[20];
    const float* attW1h = (const float*)d_in[21];
    const float* attb1  = (const float*)d_in[22];
    const float* attW2  = (const float*)d_in[23];
    const float* attb2  = (const float*)d_in[24];
    float* out = (float*)d_out;

    k_zero<<<32, 512>>>();

    { dim3 grid(32, 64); k_xproj<<<grid, 256>>>(X, W_i, W_f, W_c, W_o, b_i, b_f, b_c, b_o); }
    { dim3 grid(4, 32);  k_ctxproj<<<grid, 256>>>(context, attW1c, attb1); }

    for (int t = 0; t < TT; t++) {
        k_step_a<<<32, 256>>>(mask, context, cmask, attW1h, attW2, attb2, out, t);
        k_step_b<<<128, 256>>>(U_i, U_f, U_c, U_o, C_i, C_f, C_c, C_o);
    }
    // final gate update for t = T-1
    k_step_a<<<32, 256>>>(mask, context, cmask, attW1h, attW2, attb2, out, TT);
}

// round 15
// speedup vs baseline: 2.7069x; 2.7069x over previous
#include <cuda_runtime.h>
#include <math.h>

// Problem constants
#define BB   32
#define TT   128
#define LL   64
#define DIN  512
#define HH   512
#define DCTX 512
#define ATT  256
#define NG   2048            // 4 gates * 512
#define BT512 (BB*TT*512)    // 2097152

// Scratch (static __device__ — no allocation allowed)
__device__ float g_xcat[BB*TT*NG];      // [(b*128+t)][2048]  x-projections (+bias)
__device__ float g_ctxtr[BB*LL*ATT];    // [(b*64+l)][256]    context @ att_ctx_W1 + b1
__device__ float g_pre[4][BB*NG];       // 4-way k-split partials of h@U + ctx@C
__device__ float g_h[BB*HH];
__device__ float g_c[BB*HH];
__device__ float g_cv[BB*DCTX];

__global__ void k_zero() {
    int i = blockIdx.x * blockDim.x + threadIdx.x;
    if (i < BB*HH) { g_h[i] = 0.f; g_c[i] = 0.f; }
}

// ---------------------------------------------------------------------------
// Precompute: xcat[(b*T+t)][g*512+h] = X[b,t,:] @ W_g[:,h] + b_g[h]
// 64x64 output tile per block, 256 threads, 4x4 per thread, BK=16.
// ---------------------------------------------------------------------------
__global__ void k_xproj(const float* __restrict__ X,
                        const float* __restrict__ W0, const float* __restrict__ W1,
                        const float* __restrict__ W2, const float* __restrict__ W3,
                        const float* __restrict__ b0, const float* __restrict__ b1_,
                        const float* __restrict__ b2_, const float* __restrict__ b3)
{
    const int R0 = blockIdx.y * 64;
    const int C0 = blockIdx.x * 64;
    const int g  = C0 >> 9;
    const float* W  = (g==0)?W0:(g==1)?W1:(g==2)?W2:W3;
    const float* bs = (g==0)?b0:(g==1)?b1_:(g==2)?b2_:b3;
    const int ch0 = C0 & 511;

    __shared__ __align__(16) float As[16][64];
    __shared__ __align__(16) float Bs[16][64];

    const int tid = threadIdx.x;
    const int tx = tid & 15, ty = tid >> 4;
    float acc[4][4] = {};

    for (int k0 = 0; k0 < 512; k0 += 16) {
        {   // A tile: 64 rows x 16 k
            int row = tid >> 2;
            int kq  = (tid & 3) * 4;
            float4 v = *(const float4*)&X[(size_t)(R0+row)*512 + k0 + kq];
            As[kq+0][row]=v.x; As[kq+1][row]=v.y; As[kq+2][row]=v.z; As[kq+3][row]=v.w;
        }
        {   // B tile: 16 k x 64 cols
            int kr = tid >> 4;
            int cq = (tid & 15) * 4;
            float4 v = *(const float4*)&W[(size_t)(k0+kr)*512 + ch0 + cq];
            *(float4*)&Bs[kr][cq] = v;
        }
        __syncthreads();
        #pragma unroll
        for (int kk = 0; kk < 16; kk++) {
            float4 av = *(const float4*)&As[kk][ty*4];
            float4 bv = *(const float4*)&Bs[kk][tx*4];
            acc[0][0]+=av.x*bv.x; acc[0][1]+=av.x*bv.y; acc[0][2]+=av.x*bv.z; acc[0][3]+=av.x*bv.w;
            acc[1][0]+=av.y*bv.x; acc[1][1]+=av.y*bv.y; acc[1][2]+=av.y*bv.z; acc[1][3]+=av.y*bv.w;
            acc[2][0]+=av.z*bv.x; acc[2][1]+=av.z*bv.y; acc[2][2]+=av.z*bv.z; acc[2][3]+=av.z*bv.w;
            acc[3][0]+=av.w*bv.x; acc[3][1]+=av.w*bv.y; acc[3][2]+=av.w*bv.z; acc[3][3]+=av.w*bv.w;
        }
        __syncthreads();
    }
    float4 bias = *(const float4*)&bs[ch0 + tx*4];
    #pragma unroll
    for (int i = 0; i < 4; i++) {
        int row = R0 + ty*4 + i;
        float4 o;
        o.x = acc[i][0] + bias.x; o.y = acc[i][1] + bias.y;
        o.z = acc[i][2] + bias.z; o.w = acc[i][3] + bias.w;
        *(float4*)&g_xcat[(size_t)row*NG + C0 + tx*4] = o;
    }
}

// ctx_trans[(b*L+l)][a] = context[b,l,:] @ att_ctx_W1[:,a] + att_b1[a]
__global__ void k_ctxproj(const float* __restrict__ ctx,
                          const float* __restrict__ W,
                          const float* __restrict__ bias)
{
    const int R0 = blockIdx.y * 64;
    const int C0 = blockIdx.x * 64;

    __shared__ __align__(16) float As[16][64];
    __shared__ __align__(16) float Bs[16][64];

    const int tid = threadIdx.x;
    const int tx = tid & 15, ty = tid >> 4;
    float acc[4][4] = {};

    for (int k0 = 0; k0 < 512; k0 += 16) {
        {
            int row = tid >> 2;
            int kq  = (tid & 3) * 4;
            float4 v = *(const float4*)&ctx[(size_t)(R0+row)*512 + k0 + kq];
            As[kq+0][row]=v.x; As[kq+1][row]=v.y; As[kq+2][row]=v.z; As[kq+3][row]=v.w;
        }
        {
            int kr = tid >> 4;
            int cq = (tid & 15) * 4;
            float4 v = *(const float4*)&W[(size_t)(k0+kr)*ATT + C0 + cq];
            *(float4*)&Bs[kr][cq] = v;
        }
        __syncthreads();
        #pragma unroll
        for (int kk = 0; kk < 16; kk++) {
            float4 av = *(const float4*)&As[kk][ty*4];
            float4 bv = *(const float4*)&Bs[kk][tx*4];
            acc[0][0]+=av.x*bv.x; acc[0][1]+=av.x*bv.y; acc[0][2]+=av.x*bv.z; acc[0][3]+=av.x*bv.w;
            acc[1][0]+=av.y*bv.x; acc[1][1]+=av.y*bv.y; acc[1][2]+=av.y*bv.z; acc[1][3]+=av.y*bv.w;
            acc[2][0]+=av.z*bv.x; acc[2][1]+=av.z*bv.y; acc[2][2]+=av.z*bv.z; acc[2][3]+=av.z*bv.w;
            acc[3][0]+=av.w*bv.x; acc[3][1]+=av.w*bv.y; acc[3][2]+=av.w*bv.z; acc[3][3]+=av.w*bv.w;
        }
        __syncthreads();
    }
    float4 bias4 = *(const float4*)&bias[C0 + tx*4];
    #pragma unroll
    for (int i = 0; i < 4; i++) {
        int row = R0 + ty*4 + i;
        float4 o;
        o.x = acc[i][0] + bias4.x; o.y = acc[i][1] + bias4.y;
        o.z = acc[i][2] + bias4.z; o.w = acc[i][3] + bias4.w;
        *(float4*)&g_ctxtr[(size_t)row*ATT + C0 + tx*4] = o;
    }
}

// ---------------------------------------------------------------------------
// k_step_a: one block per batch, 1024 threads.
//   Phase 1 (t>0): apply gate activations for step t-1 (pre + xcat), update h/c.
//   Phase 2 (t<T): s = h @ att_h_W1  (64 col-quads x 16 k-slices, float4 LDG)
//   Phase 3: scores -> e (warp per 2 rows of L)
//   Phase 4: softmax-normalizer + ctx_vec (128 d-quads x 8 l-slices)
// ---------------------------------------------------------------------------
__device__ __forceinline__ float sigf(float x) { return 1.f / (1.f + expf(-x)); }

__global__ __launch_bounds__(1024)
void k_step_a(const float* __restrict__ mask,
              const float* __restrict__ context,
              const int*   __restrict__ cmask,
              const float* __restrict__ attW1h,
              const float* __restrict__ attW2,
              const float* __restrict__ attb2,
              float* __restrict__ out, int t)
{
    const int b   = blockIdx.x;
    const int tid = threadIdx.x;

    __shared__ __align__(16) float spart[16][256];   // 16 k-slice partials of s
    __shared__ __align__(16) float cpart[8][512];    // 8 l-slice partials of ctx_vec
    __shared__ __align__(16) float h_sm[512];
    __shared__ __align__(16) float s_sm[256];
    __shared__ __align__(16) float e_sm[64];
    __shared__ float inv_sm;

    // ---- Phase 1: gate update for step t-1 ----
    if (t > 0) {
        if (tid < 512) {
            const int tt = t - 1;
            const int h0 = tid;
            const float m = mask[b*TT + tt];
            const float* xrow = &g_xcat[(size_t)(b*TT + tt)*NG];
            const float* p0 = &g_pre[0][b*NG];
            const float* p1 = &g_pre[1][b*NG];
            const float* p2 = &g_pre[2][b*NG];
            const float* p3 = &g_pre[3][b*NG];
            float Pi = xrow[h0]      + p0[h0]      + p1[h0]      + p2[h0]      + p3[h0];
            float Pf = xrow[512+h0]  + p0[512+h0]  + p1[512+h0]  + p2[512+h0]  + p3[512+h0];
            float Pc = xrow[1024+h0] + p0[1024+h0] + p1[1024+h0] + p2[1024+h0] + p3[1024+h0];
            float Po = xrow[1536+h0] + p0[1536+h0] + p1[1536+h0] + p2[1536+h0] + p3[1536+h0];
            float ig = sigf(Pi);
            float fg = sigf(Pf);
            float gg = tanhf(Pc);
            float og = sigf(Po);
            float co = g_c[b*512 + h0];
            float ho = g_h[b*512 + h0];
            float cn = fg*co + ig*gg;
            float hn = og*tanhf(cn);
            hn = (1.f - m)*ho + m*hn;
            cn = (1.f - m)*co + m*cn;
            g_h[b*512 + h0] = hn;
            g_c[b*512 + h0] = cn;
            h_sm[h0] = hn;
            out[(size_t)(b*TT + tt)*512 + h0]         = hn;
            out[BT512 + (size_t)(b*TT + tt)*512 + h0] = cn;
        }
    } else {
        if (tid < 512) h_sm[tid] = 0.f;
    }
    if (t == TT) return;       // final update-only launch (uniform exit)
    __syncthreads();

    // ---- Phase 2: s[a] = h @ att_h_W1[:, a] ----
    {
        const int cq = tid & 63;        // 4 consecutive cols
        const int ks = tid >> 6;        // 16 k-slices of 32
        const int kb = ks * 32;
        float4 acc = make_float4(0.f, 0.f, 0.f, 0.f);
        #pragma unroll 8
        for (int kk = 0; kk < 32; kk++) {
            float4 w = *(const float4*)&attW1h[(size_t)(kb+kk)*ATT + cq*4];
            float hv = h_sm[kb+kk];
            acc.x += hv*w.x; acc.y += hv*w.y; acc.z += hv*w.z; acc.w += hv*w.w;
        }
        *(float4*)&spart[ks][cq*4] = acc;
    }
    __syncthreads();
    if (tid < 256) {
        float s = 0.f;
        #pragma unroll
        for (int ks = 0; ks < 16; ks++) s += spart[ks][tid];
        s_sm[tid] = s;
    }
    __syncthreads();

    // ---- Phase 3: scores e[l] = exp(W2 . tanh(ctxtr[l] + s) + b2) * cmask[l] ----
    {
        const int w = tid >> 5, lane = tid & 31;
        const float bias2 = attb2[0];
        #pragma unroll
        for (int li = 0; li < 2; li++) {
            const int l = w + li*32;
            const float* ct = &g_ctxtr[(size_t)(b*LL + l)*ATT];
            float p = 0.f;
            #pragma unroll
            for (int j = 0; j < 8; j++) {
                int a = lane + j*32;
                p += tanhf(ct[a] + s_sm[a]) * attW2[a];
            }
            #pragma unroll
            for (int off = 16; off; off >>= 1)
                p += __shfl_down_sync(0xffffffffu, p, off);
            if (lane == 0)
                e_sm[l] = expf(p + bias2) * (float)cmask[b*LL + l];
        }
    }
    __syncthreads();
    if (tid < 32) {
        float v = e_sm[tid] + e_sm[tid + 32];
        #pragma unroll
        for (int off = 16; off; off >>= 1)
            v += __shfl_down_sync(0xffffffffu, v, off);
        if (tid == 0) inv_sm = 1.f / v;
    }

    // ---- Phase 4: ctx_vec[d] = inv * sum_l e[l]*context[b,l,d] ----
    {
        const int dq = tid & 127;       // 4 consecutive d
        const int ls = tid >> 7;        // 8 l-slices of 8
        float4 acc = make_float4(0.f, 0.f, 0.f, 0.f);
        #pragma unroll
        for (int j = 0; j < 8; j++) {
            int l = ls*8 + j;
            float4 cv = *(const float4*)&context[(size_t)(b*LL + l)*512 + dq*4];
            float ev = e_sm[l];
            acc.x += ev*cv.x; acc.y += ev*cv.y; acc.z += ev*cv.z; acc.w += ev*cv.w;
        }
        *(float4*)&cpart[ls][dq*4] = acc;
    }
    __syncthreads();
    if (tid < 512) {
        const float inv = inv_sm;
        float s = 0.f;
        #pragma unroll
        for (int ls = 0; ls < 8; ls++) s += cpart[ls][tid];
        s *= inv;
        g_cv[b*512 + tid] = s;
        out[2*BT512 + (size_t)(b*TT + t)*512 + tid] = s;
    }
}

// ---------------------------------------------------------------------------
// k_step_b: pre[split][b][col] = sum_{k in quarter} h[b,k]*U_g[k,h] + cv[b,k]*C_g[k,h]
// 128 blocks = 64 column tiles (32 cols) x 2 k-halves. 512 threads:
//   cq = tid&7 (4 cols), bb = (tid>>3)&31 (batch), kt = tid>>8 (k-quarter).
// split = ks*2 + kt  -> one of 4 k-quarters of 128.
// ---------------------------------------------------------------------------
__global__ __launch_bounds__(512)
void k_step_b(const float* __restrict__ U0, const float* __restrict__ U1,
              const float* __restrict__ U2, const float* __restrict__ U3,
              const float* __restrict__ C0, const float* __restrict__ C1,
              const float* __restrict__ C2, const float* __restrict__ C3)
{
    const int bid  = blockIdx.x;
    const int ct   = bid & 63;
    const int ks   = bid >> 6;          // k-half (256)
    const int col0 = ct * 32;
    const int g    = col0 >> 9;
    const int hb   = col0 & 511;
    const float* U = (g==0)?U0:(g==1)?U1:(g==2)?U2:U3;
    const float* C = (g==0)?C0:(g==1)?C1:(g==2)?C2:C3;

    const int tid = threadIdx.x;
    const int cq  = tid & 7;            // column quad (4 cols)
    const int bb  = (tid >> 3) & 31;    // batch
    const int kt  = tid >> 8;           // k-quarter within half

    // smem: 32 batches x 256 k (this k-half), padded row stride 260 floats
    __shared__ __align__(16) float h_sm[32*260];
    __shared__ __align__(16) float cv_sm[32*260];

    // stage h and cv slices (256 k of this half) via float4
    for (int i = tid; i < 2048; i += 512) {
        int r = i >> 6, c4 = i & 63;
        *(float4*)&h_sm[r*260 + c4*4]  = *(const float4*)&g_h[r*512 + ks*256 + c4*4];
        *(float4*)&cv_sm[r*260 + c4*4] = *(const float4*)&g_cv[r*512 + ks*256 + c4*4];
    }
    __syncthreads();

    const int kbg = ks*256 + kt*128;    // global k base for this thread
    const int kbs = kt*128;             // smem k base
    const float* hrow  = &h_sm[bb*260 + kbs];
    const float* cvrow = &cv_sm[bb*260 + kbs];

    float4 acc = make_float4(0.f, 0.f, 0.f, 0.f);
    #pragma unroll 8
    for (int k4 = 0; k4 < 32; k4++) {
        float4 hv4 = *(const float4*)&hrow[k4*4];
        float4 cv4 = *(const float4*)&cvrow[k4*4];
        #pragma unroll
        for (int j = 0; j < 4; j++) {
            int kk = k4*4 + j;
            float hv = (j==0)?hv4.x:(j==1)?hv4.y:(j==2)?hv4.z:hv4.w;
            float cv = (j==0)?cv4.x:(j==1)?cv4.y:(j==2)?cv4.z:cv4.w;
            float4 wu = *(const float4*)&U[(size_t)(kbg+kk)*512 + hb + cq*4];
            float4 wc = *(const float4*)&C[(size_t)(kbg+kk)*512 + hb + cq*4];
            acc.x += hv*wu.x + cv*wc.x;
            acc.y += hv*wu.y + cv*wc.y;
            acc.z += hv*wu.z + cv*wc.z;
            acc.w += hv*wu.w + cv*wc.w;
        }
    }
    const int split = ks*2 + kt;
    *(float4*)&g_pre[split][bb*NG + col0 + cq*4] = acc;
}

// ---------------------------------------------------------------------------
extern "C" void kernel_launch(void* const* d_in, const int* in_sizes, int n_in,
                              void* d_out, int out_size)
{
    const float* X       = (const float*)d_in[0];
    const float* context = (const float*)d_in[1];
    const float* mask    = (const float*)d_in[2];
    const int*   cmask   = (const int*)  d_in[3];
    const float* W_i = (const float*)d_in[4];
    const float* U_i = (const float*)d_in[5];
    const float* C_i = (const float*)d_in[6];
    const float* b_i = (const float*)d_in[7];
    const float* W_f = (const float*)d_in[8];
    const float* U_f = (const float*)d_in[9];
    const float* C_f = (const float*)d_in[10];
    const float* b_f = (const float*)d_in[11];
    const float* W_c = (const float*)d_in[12];
    const float* U_c = (const float*)d_in[13];
    const float* C_c = (const float*)d_in[14];
    const float* b_c = (const float*)d_in[15];
    const float* W_o = (const float*)d_in[16];
    const float* U_o = (const float*)d_in[17];
    const float* C_o = (const float*)d_in[18];
    const float* b_o = (const float*)d_in[19];
    const float* attW1c = (const float*)d_in[20];
    const float* attW1h = (const float*)d_in[21];
    const float* attb1  = (const float*)d_in[22];
    const float* attW2  = (const float*)d_in[23];
    const float* attb2  = (const float*)d_in[24];
    float* out = (float*)d_out;

    k_zero<<<32, 512>>>();

    { dim3 grid(32, 64); k_xproj<<<grid, 256>>>(X, W_i, W_f, W_c, W_o, b_i, b_f, b_c, b_o); }
    { dim3 grid(4, 32);  k_ctxproj<<<grid, 256>>>(context, attW1c, attb1); }

    for (int t = 0; t < TT; t++) {
        k_step_a<<<32, 1024>>>(mask, context, cmask, attW1h, attW2, attb2, out, t);
        k_step_b<<<128, 512>>>(U_i, U_f, U_c, U_o, C_i, C_f, C_c, C_o);
    }
    // final gate update for t = T-1
    k_step_a<<<32, 1024>>>(mask, context, cmask, attW1h, attW2, attb2, out, TT);
}